// round 16
// baseline (speedup 1.0000x reference)
#include <cuda_runtime.h>
#include <cuda_fp16.h>

#define B_ROWS   32768
#define NIN      128
#define NLAYERS  8
#define WIDTH    256
#define KFAN     16
#define TILE_R   32
#define NTHREADS 512
#define UPW      16                               /* units per warp */
#define PPW      (UPW / 2)                        /* pairs per warp = 8 */
#define VALS_W   (NIN + NLAYERS * WIDTH)          /* 2176 */
#define SMEM_BYTES (VALS_W * TILE_R * 2)          /* 139264 */

__global__ __launch_bounds__(NTHREADS, 1)
void ffn_gather_fp16_w16(const float* __restrict__ inputs,
                         const float* __restrict__ weights,
                         const float* __restrict__ biases,
                         const int*   __restrict__ edge_idx,
                         float*       __restrict__ out)
{
    extern __shared__ __half vals[];              // [VALS_W][TILE_R] fp16
    __half2* vals2 = (__half2*)vals;
    const int t    = threadIdx.x;
    const int lane = t & 31;
    const int wid  = t >> 5;                      // warp 0..15: units [wid*16, wid*16+16)
    const int sub  = lane >> 4;                   // which unit of the pair
    const int j    = lane & 15;                   // half2 word -> rows 2j, 2j+1
    const int row0 = blockIdx.x * TILE_R;

    // ---- Transpose input: 32 rows x 128 feats -> vals[f][r], fp16 ----
    {
        const float4* in4 = (const float4*)(inputs + (size_t)row0 * NIN);
        #pragma unroll
        for (int it = 0; it < 2; it++) {
            int i  = t + it * NTHREADS;           // 0..1023
            int r  = i & 31;
            int c4 = i >> 5;                      // 0..31
            float4 v = in4[r * (NIN / 4) + c4];
            int f = c4 * 4;
            vals[(f + 0) * TILE_R + r] = __float2half_rn(v.x);
            vals[(f + 1) * TILE_R + r] = __float2half_rn(v.y);
            vals[(f + 2) * TILE_R + r] = __float2half_rn(v.z);
            vals[(f + 3) * TILE_R + r] = __float2half_rn(v.w);
        }
    }

    const int4*   idx4 = (const int4*)edge_idx;   // tables: [(l*256+u)*4 + q]
    const float4* w4   = (const float4*)weights;

    // ---- Prefetch tables for (l=0, pair=0, my sub) ----
    int4   ib[4];
    float4 wb[4];
    float  bs;
    {
        int g = wid * UPW + sub;
        #pragma unroll
        for (int q = 0; q < 4; q++) { ib[q] = idx4[g * 4 + q]; wb[q] = w4[g * 4 + q]; }
        bs = biases[g];
    }
    __syncthreads();

    #pragma unroll 1
    for (int l = 0; l < NLAYERS; l++) {
        #pragma unroll 1
        for (int p = 0; p < PPW; p++) {
            // unpack current tables (index pre-scaled to half2-word offset)
            int   off[KFAN];
            float fw [KFAN];
            #pragma unroll
            for (int q = 0; q < 4; q++) {
                off[q*4+0] = ib[q].x * (TILE_R/2) + j;
                off[q*4+1] = ib[q].y * (TILE_R/2) + j;
                off[q*4+2] = ib[q].z * (TILE_R/2) + j;
                off[q*4+3] = ib[q].w * (TILE_R/2) + j;
                fw [q*4+0] = wb[q].x;
                fw [q*4+1] = wb[q].y;
                fw [q*4+2] = wb[q].z;
                fw [q*4+3] = wb[q].w;
            }
            float bias = bs;

            // prefetch next pair's tables
            if (!(l == NLAYERS - 1 && p == PPW - 1)) {
                int gn = (p < PPW - 1)
                       ? (l * WIDTH + wid * UPW + 2 * (p + 1) + sub)
                       : ((l + 1) * WIDTH + wid * UPW + sub);
                #pragma unroll
                for (int q = 0; q < 4; q++) { ib[q] = idx4[gn * 4 + q]; wb[q] = w4[gn * 4 + q]; }
                bs = biases[gn];
            }

            // gather + dot for rows (2j, 2j+1) of unit u
            float ax = bias, ay = bias;
            #pragma unroll
            for (int k = 0; k < KFAN; k++) {
                float2 v = __half22float2(vals2[off[k]]);
                ax = fmaf(fw[k], v.x, ax);
                ay = fmaf(fw[k], v.y, ay);
            }

            float s0 = __fdividef(1.0f, 1.0f + __expf(-ax));
            float s1 = __fdividef(1.0f, 1.0f + __expf(-ay));

            int u = wid * UPW + 2 * p + sub;
            if (l == NLAYERS - 1) {
                // final layer: fp32 straight to output (no re-quantization)
                out[(size_t)(row0 + 2 * j)     * WIDTH + u] = s0;
                out[(size_t)(row0 + 2 * j + 1) * WIDTH + u] = s1;
            } else {
                int fo = NIN + l * WIDTH + u;     // write region disjoint from reads
                vals2[fo * (TILE_R/2) + j] = __floats2half2_rn(s0, s1);
            }
        }
        if (l < NLAYERS - 1) __syncthreads();
    }
}

extern "C" void kernel_launch(void* const* d_in, const int* in_sizes, int n_in,
                              void* d_out, int out_size)
{
    const float* inputs   = (const float*)d_in[0];
    const float* weights  = (const float*)d_in[1];
    const float* biases   = (const float*)d_in[2];
    const int*   edge_idx = (const int*)  d_in[3];
    float*       out      = (float*)d_out;

    static bool attr_set = []{
        cudaFuncSetAttribute(ffn_gather_fp16_w16,
                             cudaFuncAttributeMaxDynamicSharedMemorySize,
                             SMEM_BYTES);
        return true;
    }();
    (void)attr_set;

    ffn_gather_fp16_w16<<<B_ROWS / TILE_R, NTHREADS, SMEM_BYTES>>>(
        inputs, weights, biases, edge_idx, out);
}

// round 17
// speedup vs baseline: 1.1068x; 1.1068x over previous
#include <cuda_runtime.h>
#include <cuda_fp16.h>

#define B_ROWS   32768
#define NIN      128
#define NLAYERS  8
#define WIDTH    256
#define KFAN     16
#define TILE_R   32
#define NTHREADS 512
#define UPW      16                               /* units per warp */
#define PPW      (UPW / 2)                        /* pairs per warp = 8 */
#define VALS_W   (NIN + NLAYERS * WIDTH)          /* 2176 */
#define NDUP     1408                             /* inputs + layers 0-4 outputs */
#define PRIM_BYTES (VALS_W * TILE_R * 2)          /* 139264 */
#define DUP_BASE_B (PRIM_BYTES + 64)              /* +64B -> opposite bank phase */
#define DUP_BASE_W (DUP_BASE_B / 4)               /* in half2 words */
#define DUP_BASE_H (DUP_BASE_B / 2)               /* in half words */
#define SMEM_BYTES (DUP_BASE_B + NDUP * TILE_R * 2)   /* 229440 */

// Precomputed gather offsets (half2-word units), dup-flip baked in.
__device__ int4 g_adj[NLAYERS * WIDTH * (KFAN / 4)];

__global__ void preprocess_tables(const int* __restrict__ edge_idx)
{
    int g = blockIdx.x * blockDim.x + threadIdx.x;    // one (l,u) per thread
    if (g >= NLAYERS * WIDTH) return;
    int u  = g & (WIDTH - 1);
    const int* myi = edge_idx + g * KFAN;
    const int* pti = edge_idx + (g ^ 1) * KFAN;       // pair partner (2p,2p+1)
    bool isB = (u & 1);
    int* outp = (int*)&g_adj[g * (KFAN / 4)];
    #pragma unroll
    for (int k = 0; k < KFAN; k++) {
        int f  = myi[k];
        int fp = pti[k];
        bool conflict = (((f ^ fp) & 1) == 0);        // same 64B bank-half
        bool flip = isB ? (conflict && f < NDUP)
                        : (conflict && fp >= NDUP && f < NDUP);
        outp[k] = f * (TILE_R / 2) + (flip ? DUP_BASE_W : 0);
    }
}

__global__ __launch_bounds__(NTHREADS, 1)
void ffn_gather_dup(const float* __restrict__ inputs,
                    const float* __restrict__ weights,
                    const float* __restrict__ biases,
                    const int*   __restrict__ edge_idx,
                    float*       __restrict__ out)
{
    extern __shared__ __half vals[];              // primary [2176][32] + dup [1408][32]
    __half2* vals2 = (__half2*)vals;
    const int t    = threadIdx.x;
    const int lane = t & 31;
    const int wid  = t >> 5;                      // warp 0..15: units [wid*16, wid*16+16)
    const int sub  = lane >> 4;                   // unit of the pair
    const int j    = lane & 15;                   // half2 word -> rows 2j, 2j+1
    const int row0 = blockIdx.x * TILE_R;

    // ---- Transpose input: 32 rows x 128 feats -> vals[f][r] (+ dup copy) ----
    {
        const float4* in4 = (const float4*)(inputs + (size_t)row0 * NIN);
        #pragma unroll
        for (int it = 0; it < 2; it++) {
            int i  = t + it * NTHREADS;           // 0..1023
            int r  = i & 31;
            int c4 = i >> 5;                      // 0..31
            float4 v = in4[r * (NIN / 4) + c4];
            int f = c4 * 4;
            __half h0 = __float2half_rn(v.x);
            __half h1 = __float2half_rn(v.y);
            __half h2 = __float2half_rn(v.z);
            __half h3 = __float2half_rn(v.w);
            vals[(f + 0) * TILE_R + r] = h0;
            vals[(f + 1) * TILE_R + r] = h1;
            vals[(f + 2) * TILE_R + r] = h2;
            vals[(f + 3) * TILE_R + r] = h3;
            // all 128 input features are < NDUP -> duplicate
            vals[DUP_BASE_H + (f + 0) * TILE_R + r] = h0;
            vals[DUP_BASE_H + (f + 1) * TILE_R + r] = h1;
            vals[DUP_BASE_H + (f + 2) * TILE_R + r] = h2;
            vals[DUP_BASE_H + (f + 3) * TILE_R + r] = h3;
        }
    }

    const float4* w4 = (const float4*)weights;

    // ---- Prefetch tables for (l=0, pair=0, my sub) ----
    int4   ib[4];
    float4 wb[4];
    float  bs;
    {
        int g = wid * UPW + sub;
        #pragma unroll
        for (int q = 0; q < 4; q++) { ib[q] = g_adj[g * 4 + q]; wb[q] = w4[g * 4 + q]; }
        bs = biases[g];
    }
    __syncthreads();

    #pragma unroll 1
    for (int l = 0; l < NLAYERS; l++) {
        #pragma unroll 1
        for (int p = 0; p < PPW; p++) {
            // unpack current tables (offsets pre-scaled + dup-flip baked in)
            int   off[KFAN];
            float fw [KFAN];
            #pragma unroll
            for (int q = 0; q < 4; q++) {
                off[q*4+0] = ib[q].x + j;
                off[q*4+1] = ib[q].y + j;
                off[q*4+2] = ib[q].z + j;
                off[q*4+3] = ib[q].w + j;
                fw [q*4+0] = wb[q].x;
                fw [q*4+1] = wb[q].y;
                fw [q*4+2] = wb[q].z;
                fw [q*4+3] = wb[q].w;
            }
            float bias = bs;

            // prefetch next pair's tables
            if (!(l == NLAYERS - 1 && p == PPW - 1)) {
                int gn = (p < PPW - 1)
                       ? (l * WIDTH + wid * UPW + 2 * (p + 1) + sub)
                       : ((l + 1) * WIDTH + wid * UPW + sub);
                #pragma unroll
                for (int q = 0; q < 4; q++) { ib[q] = g_adj[gn * 4 + q]; wb[q] = w4[gn * 4 + q]; }
                bs = biases[gn];
            }

            // gather + dot for rows (2j, 2j+1) of this unit
            float ax = bias, ay = bias;
            #pragma unroll
            for (int k = 0; k < KFAN; k++) {
                float2 v = __half22float2(vals2[off[k]]);
                ax = fmaf(fw[k], v.x, ax);
                ay = fmaf(fw[k], v.y, ay);
            }

            float s0 = __fdividef(1.0f, 1.0f + __expf(-ax));
            float s1 = __fdividef(1.0f, 1.0f + __expf(-ay));

            int u = wid * UPW + 2 * p + sub;
            if (l == NLAYERS - 1) {
                // final layer: fp32 straight to output
                out[(size_t)(row0 + 2 * j)     * WIDTH + u] = s0;
                out[(size_t)(row0 + 2 * j + 1) * WIDTH + u] = s1;
            } else {
                int fo = NIN + l * WIDTH + u;
                __half2 hp = __floats2half2_rn(s0, s1);
                vals2[fo * (TILE_R/2) + j] = hp;
                if (l < 5)                        // fo < NDUP -> keep dup coherent
                    vals2[DUP_BASE_W + fo * (TILE_R/2) + j] = hp;
            }
        }
        if (l < NLAYERS - 1) __syncthreads();
    }
}

extern "C" void kernel_launch(void* const* d_in, const int* in_sizes, int n_in,
                              void* d_out, int out_size)
{
    const float* inputs   = (const float*)d_in[0];
    const float* weights  = (const float*)d_in[1];
    const float* biases   = (const float*)d_in[2];
    const int*   edge_idx = (const int*)  d_in[3];
    float*       out      = (float*)d_out;

    static bool attr_set = []{
        cudaFuncSetAttribute(ffn_gather_dup,
                             cudaFuncAttributeMaxDynamicSharedMemorySize,
                             SMEM_BYTES);
        return true;
    }();
    (void)attr_set;

    preprocess_tables<<<(NLAYERS * WIDTH + 255) / 256, 256>>>(edge_idx);
    ffn_gather_dup<<<B_ROWS / TILE_R, NTHREADS, SMEM_BYTES>>>(
        inputs, weights, biases, edge_idx, out);
}